// round 1
// baseline (speedup 1.0000x reference)
#include <cuda_runtime.h>

// Multi-level hash-grid encoding (instant-NGP style), GB300 sm_103a.
// Strategy: one block per (level, point-chunk). The level's embedding table
// (<= 16384 x float2 = 128KB) is staged in dynamic shared memory, so the 8
// random corner gathers per point-level are LDS.64 (smem crossbar) instead of
// divergent global loads (L1tex wavefront bound).
// Grid = (16 levels fast, 37 chunks): all 16 levels of a chunk run
// concurrently, so the 8B-per-level strided output writes to the same 128B
// line merge in L2 before eviction (avoids 4x DRAM write amplification).

#define NLV 16
#define TBL 16384          // max table rows per level (padded stacking)
#define BT  512            // threads per block
#define NCHUNK 37          // 16*37 = 592 blocks = 4 exact waves on 148 SMs

// res[i] = floor(16 * 2^(i/3)); n_enc = min(res^3, 16384); hashing iff res^3 > 16384
__constant__ int c_res[NLV]  = {16, 20, 25, 32, 40, 50, 64, 80,
                                101, 128, 161, 203, 256, 322, 406, 512};
__constant__ int c_nenc[NLV] = {4096, 8000, 15625, 16384, 16384, 16384, 16384, 16384,
                                16384, 16384, 16384, 16384, 16384, 16384, 16384, 16384};

__global__ __launch_bounds__(BT, 1)
void hashenc_kernel(const float* __restrict__ x,
                    const float* __restrict__ emb,
                    float2* __restrict__ out,
                    int npts, int ppb)
{
    const int level   = blockIdx.x;
    const int res     = c_res[level];
    const int nenc    = c_nenc[level];
    const bool hashing = (level >= 3);

    extern __shared__ float2 tab[];
    const float2* src = reinterpret_cast<const float2*>(emb) + level * TBL;
    for (int i = threadIdx.x; i < nenc; i += BT)
        tab[i] = __ldg(src + i);
    __syncthreads();

    const float resf = (float)res;
    const int b0 = blockIdx.y * ppb;
    const int b1 = min(npts, b0 + ppb);

    for (int b = b0 + (int)threadIdx.x; b < b1; b += BT) {
        const float px = x[3 * b + 0];
        const float py = x[3 * b + 1];
        const float pz = x[3 * b + 2];

        // grid coords: s in [-0.5, res-0.5], so c in [-1, res-1]
        const float sx = (px + 1.0f) * resf * 0.5f - 0.5f;
        const float sy = (py + 1.0f) * resf * 0.5f - 0.5f;
        const float sz = (pz + 1.0f) * resf * 0.5f - 0.5f;
        const float flx = floorf(sx), fly = floorf(sy), flz = floorf(sz);
        const float fx = sx - flx, fy = sy - fly, fz = sz - flz;
        const int cx = (int)flx, cy = (int)fly, cz = (int)flz;

        // per-dim trilinear weights with boundary masking folded in:
        // offset 0 valid iff c >= 0; offset 1 valid iff c+1 < res (c <= res-2)
        const float wx0 = (cx >= 0)       ? 1.0f - fx : 0.0f;
        const float wx1 = (cx <  res - 1) ? fx        : 0.0f;
        const float wy0 = (cy >= 0)       ? 1.0f - fy : 0.0f;
        const float wy1 = (cy <  res - 1) ? fy        : 0.0f;
        const float wz0 = (cz >= 0)       ? 1.0f - fz : 0.0f;
        const float wz1 = (cz <  res - 1) ? fz        : 0.0f;

        const float w00 = wx0 * wy0, w01 = wx0 * wy1;
        const float w10 = wx1 * wy0, w11 = wx1 * wy1;

        unsigned id[8];
        if (hashing) {
            // h = c0 ^ (c1*2654435761) ^ (c2*805459861), uint32 wrap; nenc = 2^14
            const unsigned hx0 = (unsigned)cx;
            const unsigned hx1 = (unsigned)(cx + 1);
            const unsigned hy0 = (unsigned)cy       * 2654435761u;
            const unsigned hy1 = (unsigned)(cy + 1) * 2654435761u;
            const unsigned hz0 = (unsigned)cz       * 805459861u;
            const unsigned hz1 = (unsigned)(cz + 1) * 805459861u;
            const unsigned g00 = hx0 ^ hy0, g01 = hx0 ^ hy1;
            const unsigned g10 = hx1 ^ hy0, g11 = hx1 ^ hy1;
            const unsigned m = (unsigned)(nenc - 1);   // 16383
            id[0] = (g00 ^ hz0) & m;  id[1] = (g00 ^ hz1) & m;
            id[2] = (g01 ^ hz0) & m;  id[3] = (g01 ^ hz1) & m;
            id[4] = (g10 ^ hz0) & m;  id[5] = (g10 ^ hz1) & m;
            id[6] = (g11 ^ hz0) & m;  id[7] = (g11 ^ hz1) & m;
        } else {
            // ravel: id = c0 + c1*res + c2*res^2; valid ids < res^3 == nenc,
            // so mod is identity. Invalid corners have weight 0 — just clamp
            // the index into range so the smem read is safe.
            const int r2 = res * res;
            const int a0 = cx,        a1 = cx + 1;
            const int b0v = cy * res, b1v = (cy + 1) * res;
            const int c0v = cz * r2,  c1v = (cz + 1) * r2;
            const unsigned lim = (unsigned)(nenc - 1);
            id[0] = min((unsigned)(a0 + b0v + c0v), lim);
            id[1] = min((unsigned)(a0 + b0v + c1v), lim);
            id[2] = min((unsigned)(a0 + b1v + c0v), lim);
            id[3] = min((unsigned)(a0 + b1v + c1v), lim);
            id[4] = min((unsigned)(a1 + b0v + c0v), lim);
            id[5] = min((unsigned)(a1 + b0v + c1v), lim);
            id[6] = min((unsigned)(a1 + b1v + c0v), lim);
            id[7] = min((unsigned)(a1 + b1v + c1v), lim);
        }

        // weights in corner-offset order [[0,0,0],[0,0,1],[0,1,0],...,[1,1,1]]
        const float w[8] = { w00 * wz0, w00 * wz1, w01 * wz0, w01 * wz1,
                             w10 * wz0, w10 * wz1, w11 * wz0, w11 * wz1 };

        float ax = 0.0f, ay = 0.0f;
        #pragma unroll
        for (int k = 0; k < 8; k++) {
            const float2 e = tab[id[k]];
            ax = fmaf(w[k], e.x, ax);
            ay = fmaf(w[k], e.y, ay);
        }

        out[b * NLV + level] = make_float2(ax, ay);
    }
}

extern "C" void kernel_launch(void* const* d_in, const int* in_sizes, int n_in,
                              void* d_out, int out_size)
{
    const float* x   = (const float*)d_in[0];   // (B, 3) float32
    const float* emb = (const float*)d_in[1];   // (16, 16384, 2) float32
    float2* out      = (float2*)d_out;          // (B, 16, 2) float32

    const int npts = in_sizes[0] / 3;
    const int ppb  = (npts + NCHUNK - 1) / NCHUNK;
    const int smem = TBL * (int)sizeof(float2); // 128 KB

    cudaFuncSetAttribute(hashenc_kernel,
                         cudaFuncAttributeMaxDynamicSharedMemorySize, smem);

    hashenc_kernel<<<dim3(NLV, NCHUNK), BT, smem>>>(x, emb, out, npts, ppb);
}